// round 10
// baseline (speedup 1.0000x reference)
#include <cuda_runtime.h>

#define XS 8192

// Scratch (allocation-free)
__device__ float g_Tpart[16 * 8 * 2 * 1024];   // [k][Bg][pq][s][o]
__device__ unsigned int g_cnt[16];             // per-k counters (8 producers each)

static __device__ __forceinline__ unsigned int ld_acq(const unsigned int* p) {
    unsigned int v;
    asm volatile("ld.acquire.gpu.u32 %0, [%1];" : "=r"(v) : "l"(p));
    return v;
}
static __device__ __forceinline__ unsigned int atom_add_rel(unsigned int* p, unsigned int v) {
    unsigned int o;
    asm volatile("atom.release.gpu.add.u32 %0, [%1], %2;"
                 : "=r"(o) : "l"(p), "r"(v) : "memory");
    return o;
}
static __device__ __forceinline__ unsigned long long fma_x2(
    unsigned long long a, unsigned long long b, unsigned long long c) {
    unsigned long long d;
    asm("fma.rn.f32x2 %0, %1, %2, %3;" : "=l"(d) : "l"(a), "l"(b), "l"(c));
    return d;
}

__device__ __forceinline__ float4 shfl_xor_add_f4(float4 v, int d) {
    float4 r;
    r.x = v.x + __shfl_xor_sync(0xffffffffu, v.x, d);
    r.y = v.y + __shfl_xor_sync(0xffffffffu, v.y, d);
    r.z = v.z + __shfl_xor_sync(0xffffffffu, v.z, d);
    r.w = v.w + __shfl_xor_sync(0xffffffffu, v.w, d);
    return r;
}

__global__ void __launch_bounds__(512, 1) fused_kernel(
    const float* __restrict__ x,
    const float* __restrict__ w_diag,
    const float* __restrict__ w_off,
    const float* __restrict__ b1,
    const int*   __restrict__ perm,
    float*       __restrict__ out)
{
    // f4 union (rows of 17 f4, m-pair packed float2 per i):
    //   Wp[0,544) Wm[544,1088) Sp[1088,1632) Sm[1632,2176); reused as stage floats
    __shared__ float4 SM4[2176];
    __shared__ float4 wdsh4[264];    // [iq*33 + o]
    __shared__ float4 tsh4[64];      // [p*32 + sL*8 + oq]
    __shared__ float  bsh[32];
    float* SMf  = (float*)SM4;
    float* tshF = (float*)tsh4;

    const int b = blockIdx.x, t = threadIdx.x;
    const int k = b >> 3, sg = b & 7;          // producer Bg == consumer sg

    if (t < 32) bsh[t] = __ldg(&b1[t]);

    // ---- finalize-role indices + x row prefetch (earliest possible) ----
    const int sL = t >> 7, aa = (t >> 3) & 15, og = t & 7;
    const int n2 = __ldg(&perm[k * 16 + aa]);
    float4 xr[8];
    {
        const float4* xrow = (const float4*)(x + (4 * sg + sL) * XS + n2 * 32);
#pragma unroll
        for (int iq = 0; iq < 8; iq++) xr[iq] = __ldg(&xrow[iq]);
    }

    // ---- W prefetch for contraction ----
    const float4* woff4 = (const float4*)w_off;     // [c][k][B/4]
    float4 wreg[2];
#pragma unroll
    for (int j = 0; j < 2; j++)
        wreg[j] = __ldg(&woff4[(j * 512 + t) * 128 + k * 8 + sg]);

    // ---- w_diag column k straight into smem ----
    {
        float* wdf = (float*)wdsh4;
#pragma unroll
        for (int j = 0; j < 2; j++) {
            int c = j * 512 + t;                    // c = o*32 + i
            int o = c >> 5, i = c & 31;
            wdf[((i >> 2) * 33 + o) * 4 + (i & 3)] = __ldg(&w_diag[c * 16 + k]);
        }
    }

    // ================= phase A: local gather + S± pooling ===================
    {
        const int sA = t >> 4, iqA = t & 7, rh = (t >> 3) & 1;
        const float4* x4 = (const float4*)x;
        float4 sB[4];
#pragma unroll
        for (int Bl = 0; Bl < 4; Bl++) {
            float4 a = make_float4(0.f, 0.f, 0.f, 0.f);
#pragma unroll
            for (int rr = 0; rr < 4; rr++) {
                int n = __ldg(&perm[sg * 32 + Bl * 8 + rh * 4 + rr]);
                float4 v = __ldg(&x4[sA * 2048 + n * 8 + iqA]);
                a.x += v.x; a.y += v.y; a.z += v.z; a.w += v.w;
            }
            sB[Bl] = a;
        }
#pragma unroll
        for (int Bl = 0; Bl < 4; Bl++) sB[Bl] = shfl_xor_add_f4(sB[Bl], 8);

        // m-pair packed rows: f4 = (v_m0(i), v_m1(i), v_m0(i+1), v_m1(i+1)),
        // i-range of this thread = 4*iqA..4*iqA+3  ->  f4 slots 2*iqA, 2*iqA+1
        if (rh == 0) {   // Sp
            float4 p0, p1;   // p0 = m0 over 4 i's, p1 = m1
            p0.x = sB[0].x + sB[1].x; p0.y = sB[0].y + sB[1].y;
            p0.z = sB[0].z + sB[1].z; p0.w = sB[0].w + sB[1].w;
            p1.x = sB[2].x + sB[3].x; p1.y = sB[2].y + sB[3].y;
            p1.z = sB[2].z + sB[3].z; p1.w = sB[2].w + sB[3].w;
            SM4[1088 + sA * 17 + 2 * iqA    ] = make_float4(p0.x, p1.x, p0.y, p1.y);
            SM4[1088 + sA * 17 + 2 * iqA + 1] = make_float4(p0.z, p1.z, p0.w, p1.w);
        } else {         // Sm
            float4 q0, q1;
            q0.x = sB[0].x - sB[1].x; q0.y = sB[0].y - sB[1].y;
            q0.z = sB[0].z - sB[1].z; q0.w = sB[0].w - sB[1].w;
            q1.x = sB[2].x - sB[3].x; q1.y = sB[2].y - sB[3].y;
            q1.z = sB[2].z - sB[3].z; q1.w = sB[2].w - sB[3].w;
            SM4[1632 + sA * 17 + 2 * iqA    ] = make_float4(q0.x, q1.x, q0.y, q1.y);
            SM4[1632 + sA * 17 + 2 * iqA + 1] = make_float4(q0.z, q1.z, q0.w, q1.w);
        }
    }

    // ---- W± -> smem (m-pair packed float2 per i) ----
    {
        float2* Wp2 = (float2*)SM4;              // row o: 34 float2
        float2* Wm2 = (float2*)(SM4 + 544);
#pragma unroll
        for (int jj = 0; jj < 2; jj++) {
            int c = jj * 512 + t, o = c >> 5, i = c & 31;
            float4 w = wreg[jj];                  // (b0,b1,b2,b3) = m0-pair, m1-pair
            Wp2[o * 34 + i] = make_float2(w.x + w.y, w.z + w.w);
            Wm2[o * 34 + i] = make_float2(w.x - w.y, w.z - w.w);
        }
    }
    __syncthreads();

    // ================= phase B: contraction (f32x2, both m-halves/lane) =====
    float accf[16];
    {
        const int pq = t >> 8, sh = (t >> 5) & 7, ogB = (t >> 2) & 7, ih = t & 3;
        const ulonglong2* Wb = (const ulonglong2*)(SM4 + (pq ? 544 : 0));
        const ulonglong2* Sb = (const ulonglong2*)(SM4 + 1088 + (pq ? 544 : 0));
        unsigned long long acc[16];
#pragma unroll
        for (int j = 0; j < 16; j++) acc[j] = 0ull;
#pragma unroll
        for (int c4 = 0; c4 < 4; c4++) {
            int iq = ih * 4 + c4;                 // f4/ull2 slot within 16-slot row
            ulonglong2 s2[4], w2[4];
#pragma unroll
            for (int ss = 0; ss < 4; ss++) s2[ss] = Sb[(sh + 8 * ss) * 17 + iq];
#pragma unroll
            for (int oo = 0; oo < 4; oo++) w2[oo] = Wb[(ogB + 8 * oo) * 17 + iq];
#pragma unroll
            for (int ss = 0; ss < 4; ss++)
#pragma unroll
                for (int oo = 0; oo < 4; oo++) {
                    unsigned long long a = acc[ss * 4 + oo];
                    a = fma_x2(w2[oo].x, s2[ss].x, a);
                    a = fma_x2(w2[oo].y, s2[ss].y, a);
                    acc[ss * 4 + oo] = a;
                }
        }
#pragma unroll
        for (int j = 0; j < 16; j++) {            // collapse (m0,m1)
            float2 u = *(float2*)&acc[j];
            accf[j] = u.x + u.y;
        }
    }
    __syncthreads();
#pragma unroll
    for (int jj = 0; jj < 16; jj++)
        SMf[jj * 513 + t] = accf[jj];
    __syncthreads();
    // reduce over ih (4) and store Tpart: [k][Bg][pq][s][o]
    {
        const int pq = t >> 8, sh = (t >> 5) & 7, oo2 = (t >> 3) & 3, ogr = t & 7;
        const int g = pq * 64 + sh * 8 + ogr;
        float* Tdst = g_Tpart + ((k * 8 + sg) * 2 + pq) * 1024;
#pragma unroll
        for (int ss = 0; ss < 4; ss++) {
            int j = ss * 4 + oo2;
            float v = SMf[j * 513 + g * 4 + 0] + SMf[j * 513 + g * 4 + 1]
                    + SMf[j * 513 + g * 4 + 2] + SMf[j * 513 + g * 4 + 3];
            Tdst[(sh + 8 * ss) * 32 + (ogr + 8 * oo2)] = v;
        }
    }
    __syncthreads();

    // ---- release our Tpart; overlap diag GEMM with other producers --------
    unsigned int tgt = 0;
    if (t == 0) {
        unsigned int my = atom_add_rel(&g_cnt[k], 1u);
        tgt = ((my >> 3) + 1u) << 3;       // 8 producers per k
    }

    float acc2[4];
#pragma unroll
    for (int oo = 0; oo < 4; oo++) acc2[oo] = bsh[og + 8 * oo];
#pragma unroll
    for (int iq = 0; iq < 8; iq++) {
        float4 xv = xr[iq];
#pragma unroll
        for (int oo = 0; oo < 4; oo++) {
            float4 wv = wdsh4[iq * 33 + og + 8 * oo];
            acc2[oo] += wv.x * xv.x + wv.y * xv.y + wv.z * xv.z + wv.w * xv.w;
        }
    }

    if (t == 0) { while (ld_acq(&g_cnt[k]) < tgt) {} }
    __syncthreads();

    // ---- T reduce (one warp, MLP 16): T[p][sL][o] = (P ± Q)/512 ------------
    if (t < 32) {
        int sL2 = t >> 3, oq = t & 7;
        const float4* Tp4 = (const float4*)g_Tpart;
        float4 P = make_float4(0.f, 0.f, 0.f, 0.f);
        float4 Q = make_float4(0.f, 0.f, 0.f, 0.f);
#pragma unroll
        for (int Bg = 0; Bg < 8; Bg++) {
            float4 vp = __ldcg(&Tp4[((k * 8 + Bg) * 2 + 0) * 256 + (4 * sg + sL2) * 8 + oq]);
            float4 vq = __ldcg(&Tp4[((k * 8 + Bg) * 2 + 1) * 256 + (4 * sg + sL2) * 8 + oq]);
            P.x += vp.x; P.y += vp.y; P.z += vp.z; P.w += vp.w;
            Q.x += vq.x; Q.y += vq.y; Q.z += vq.z; Q.w += vq.w;
        }
        const float c = 1.0f / 512.0f;
        float4 T0, T1;
        T0.x = (P.x + Q.x) * c; T0.y = (P.y + Q.y) * c;
        T0.z = (P.z + Q.z) * c; T0.w = (P.w + Q.w) * c;
        T1.x = (P.x - Q.x) * c; T1.y = (P.y - Q.y) * c;
        T1.z = (P.z - Q.z) * c; T1.w = (P.w - Q.w) * c;
        tsh4[     sL2 * 8 + oq] = T0;
        tsh4[32 + sL2 * 8 + oq] = T1;
    }
    __syncthreads();

    // ---- add T term + store -------------------------------------------------
    const int pa = aa >> 3;
    float* orow = out + (4 * sg + sL) * XS + n2 * 32;
#pragma unroll
    for (int oo = 0; oo < 4; oo++)
        orow[og + 8 * oo] = acc2[oo] + tshF[pa * 128 + sL * 32 + og + 8 * oo];
}

// ---------------------------------------------------------------------------
extern "C" void kernel_launch(void* const* d_in, const int* in_sizes, int n_in,
                              void* d_out, int out_size)
{
    const float* x      = (const float*)d_in[0];
    const float* w_diag = (const float*)d_in[1];
    const float* w_off  = (const float*)d_in[2];
    const float* b1     = (const float*)d_in[3];
    const int*   perm   = (const int*)d_in[4];
    float* out = (float*)d_out;

    fused_kernel<<<128, 512>>>(x, w_diag, w_off, b1, perm, out);
}

// round 11
// speedup vs baseline: 1.1895x; 1.1895x over previous
#include <cuda_runtime.h>

#define XS 8192

// Scratch (allocation-free)
__device__ float g_Tpart[16 * 8 * 2 * 1024];   // [k][Bg][pq][s][o]
__device__ unsigned int g_cnt[16];             // per-k counters (8 producers each)

static __device__ __forceinline__ unsigned int ld_acq(const unsigned int* p) {
    unsigned int v;
    asm volatile("ld.acquire.gpu.u32 %0, [%1];" : "=r"(v) : "l"(p));
    return v;
}
static __device__ __forceinline__ unsigned int atom_add_rel(unsigned int* p, unsigned int v) {
    unsigned int o;
    asm volatile("atom.release.gpu.add.u32 %0, [%1], %2;"
                 : "=r"(o) : "l"(p), "r"(v) : "memory");
    return o;
}

__device__ __forceinline__ float4 shfl_xor_add_f4(float4 v, int d) {
    float4 r;
    r.x = v.x + __shfl_xor_sync(0xffffffffu, v.x, d);
    r.y = v.y + __shfl_xor_sync(0xffffffffu, v.y, d);
    r.z = v.z + __shfl_xor_sync(0xffffffffu, v.z, d);
    r.w = v.w + __shfl_xor_sync(0xffffffffu, v.w, d);
    return r;
}

__global__ void __launch_bounds__(512, 1) fused_kernel(
    const float* __restrict__ x,
    const float* __restrict__ w_diag,
    const float* __restrict__ w_off,
    const float* __restrict__ b1,
    const int*   __restrict__ perm,
    float*       __restrict__ out)
{
    // f4 union: Wp[0,544) Wm[544,1088) Sp[1088,1632) Sm[1632,2176)
    __shared__ float4 SM4[2176];
    __shared__ float4 wdsh4[264];    // [(iq)*33 + o]
    __shared__ float4 tsh4[64];      // [p*32 + sL*8 + oq]
    __shared__ float  bsh[32];
    float* SMf  = (float*)SM4;
    float* tshF = (float*)tsh4;
    (void)SMf;

    const int b = blockIdx.x, t = threadIdx.x;
    const int k = b >> 3, sg = b & 7;          // producer Bg == consumer sg

    if (t < 32) bsh[t] = __ldg(&b1[t]);

    // ---- finalize-role indices + x row prefetch (earliest possible) ----
    const int sL = t >> 7, aa = (t >> 3) & 15, og = t & 7;
    const int n2 = __ldg(&perm[k * 16 + aa]);
    float4 xr[8];
    {
        const float4* xrow = (const float4*)(x + (4 * sg + sL) * XS + n2 * 32);
#pragma unroll
        for (int iq = 0; iq < 8; iq++) xr[iq] = __ldg(&xrow[iq]);
    }

    // ---- W prefetch for contraction ----
    const float4* woff4 = (const float4*)w_off;     // [c][k][B/4]
    float4 wreg[2];
#pragma unroll
    for (int j = 0; j < 2; j++)
        wreg[j] = __ldg(&woff4[(j * 512 + t) * 128 + k * 8 + sg]);

    // ---- w_diag column k straight into smem (no global staging) ----
    {
        float* wdf = (float*)wdsh4;
#pragma unroll
        for (int j = 0; j < 2; j++) {
            int c = j * 512 + t;                    // c = o*32 + i
            int o = c >> 5, i = c & 31;
            wdf[((i >> 2) * 33 + o) * 4 + (i & 3)] = __ldg(&w_diag[c * 16 + k]);
        }
    }

    // ================= phase A: local gather + S± pooling ===================
    {
        const int sA = t >> 4, iqA = t & 7, rh = (t >> 3) & 1;
        const float4* x4 = (const float4*)x;
        float4 sB[4];
#pragma unroll
        for (int Bl = 0; Bl < 4; Bl++) {
            float4 a = make_float4(0.f, 0.f, 0.f, 0.f);
#pragma unroll
            for (int rr = 0; rr < 4; rr++) {
                int n = __ldg(&perm[sg * 32 + Bl * 8 + rh * 4 + rr]);
                float4 v = __ldg(&x4[sA * 2048 + n * 8 + iqA]);
                a.x += v.x; a.y += v.y; a.z += v.z; a.w += v.w;
            }
            sB[Bl] = a;
        }
#pragma unroll
        for (int Bl = 0; Bl < 4; Bl++) sB[Bl] = shfl_xor_add_f4(sB[Bl], 8);

        if (rh == 0) {   // Sp rows: [s*17 + m*8 + iq]
            float4 p0, p1;
            p0.x = sB[0].x + sB[1].x; p0.y = sB[0].y + sB[1].y;
            p0.z = sB[0].z + sB[1].z; p0.w = sB[0].w + sB[1].w;
            p1.x = sB[2].x + sB[3].x; p1.y = sB[2].y + sB[3].y;
            p1.z = sB[2].z + sB[3].z; p1.w = sB[2].w + sB[3].w;
            SM4[1088 + sA * 17 +     iqA] = p0;
            SM4[1088 + sA * 17 + 8 + iqA] = p1;
        } else {         // Sm rows
            float4 q0, q1;
            q0.x = sB[0].x - sB[1].x; q0.y = sB[0].y - sB[1].y;
            q0.z = sB[0].z - sB[1].z; q0.w = sB[0].w - sB[1].w;
            q1.x = sB[2].x - sB[3].x; q1.y = sB[2].y - sB[3].y;
            q1.z = sB[2].z - sB[3].z; q1.w = sB[2].w - sB[3].w;
            SM4[1632 + sA * 17 +     iqA] = q0;
            SM4[1632 + sA * 17 + 8 + iqA] = q1;
        }
    }

    // ---- W± -> smem ----
    {
        float* Wp = (float*)SM4;       // row o: 68 floats
        float* Wm = (float*)(SM4 + 544);
#pragma unroll
        for (int jj = 0; jj < 2; jj++) {
            int c = jj * 512 + t, o = c >> 5, i = c & 31;
            float4 w = wreg[jj];
            Wp[o * 68 +      i] = w.x + w.y;   // m=0
            Wp[o * 68 + 32 + i] = w.z + w.w;   // m=1
            Wm[o * 68 +      i] = w.x - w.y;
            Wm[o * 68 + 32 + i] = w.z - w.w;
        }
    }
    __syncthreads();

    // ================= phase B: contraction (all 512 threads) ===============
    float acc[4][4];
    {
        const int pq = t >> 8, sh = (t >> 5) & 7, ogB = (t >> 2) & 7, ih = t & 3;
        const float4* Wb = SM4 + (pq ? 544 : 0);
        const float4* Sb = SM4 + 1088 + (pq ? 544 : 0);
#pragma unroll
        for (int j = 0; j < 16; j++) ((float*)acc)[j] = 0.f;
#pragma unroll
        for (int m = 0; m < 2; m++)
#pragma unroll
            for (int j = 0; j < 2; j++) {
                int iq = ih * 2 + j;
                float4 s4[4], w4[4];
#pragma unroll
                for (int ss = 0; ss < 4; ss++)
                    s4[ss] = Sb[(sh + 8 * ss) * 17 + m * 8 + iq];
#pragma unroll
                for (int oo = 0; oo < 4; oo++)
                    w4[oo] = Wb[(ogB + 8 * oo) * 17 + m * 8 + iq];
#pragma unroll
                for (int ss = 0; ss < 4; ss++)
#pragma unroll
                    for (int oo = 0; oo < 4; oo++)
                        acc[ss][oo] += w4[oo].x * s4[ss].x + w4[oo].y * s4[ss].y
                                     + w4[oo].z * s4[ss].z + w4[oo].w * s4[ss].w;
            }

        // ---- ih reduce via warp butterfly (lanes t^1, t^2) — no smem stage --
#pragma unroll
        for (int u = 0; u < 16; u++) {
            float v = ((float*)acc)[u];
            v += __shfl_xor_sync(0xffffffffu, v, 1);
            v += __shfl_xor_sync(0xffffffffu, v, 2);
            ((float*)acc)[u] = v;
        }
        // lane ih stores the ss==ih quarter (static indexing, predicated)
        float* Tdst = g_Tpart + ((k * 8 + sg) * 2 + pq) * 1024;
#pragma unroll
        for (int ss = 0; ss < 4; ss++) {
            if (ih == ss) {
#pragma unroll
                for (int oo = 0; oo < 4; oo++)
                    Tdst[(sh + 8 * ss) * 32 + ogB + 8 * oo] = acc[ss][oo];
            }
        }
    }
    __syncthreads();

    // ---- release our Tpart; overlap diag GEMM with other producers --------
    unsigned int tgt = 0;
    if (t == 0) {
        unsigned int my = atom_add_rel(&g_cnt[k], 1u);
        tgt = ((my >> 3) + 1u) << 3;       // 8 producers per k
    }

    float acc2[4];
#pragma unroll
    for (int oo = 0; oo < 4; oo++) acc2[oo] = bsh[og + 8 * oo];
#pragma unroll
    for (int iq = 0; iq < 8; iq++) {
        float4 xv = xr[iq];
#pragma unroll
        for (int oo = 0; oo < 4; oo++) {
            float4 wv = wdsh4[iq * 33 + og + 8 * oo];
            acc2[oo] += wv.x * xv.x + wv.y * xv.y + wv.z * xv.z + wv.w * xv.w;
        }
    }

    if (t == 0) { while (ld_acq(&g_cnt[k]) < tgt) {} }
    __syncthreads();

    // ---- T reduce (one warp, MLP 16): T[p][sL][o] = (P ± Q)/512 ------------
    if (t < 32) {
        int sL2 = t >> 3, oq = t & 7;
        const float4* Tp4 = (const float4*)g_Tpart;
        float4 P = make_float4(0.f, 0.f, 0.f, 0.f);
        float4 Q = make_float4(0.f, 0.f, 0.f, 0.f);
#pragma unroll
        for (int Bg = 0; Bg < 8; Bg++) {
            float4 vp = __ldcg(&Tp4[((k * 8 + Bg) * 2 + 0) * 256 + (4 * sg + sL2) * 8 + oq]);
            float4 vq = __ldcg(&Tp4[((k * 8 + Bg) * 2 + 1) * 256 + (4 * sg + sL2) * 8 + oq]);
            P.x += vp.x; P.y += vp.y; P.z += vp.z; P.w += vp.w;
            Q.x += vq.x; Q.y += vq.y; Q.z += vq.z; Q.w += vq.w;
        }
        const float c = 1.0f / 512.0f;
        float4 T0, T1;
        T0.x = (P.x + Q.x) * c; T0.y = (P.y + Q.y) * c;
        T0.z = (P.z + Q.z) * c; T0.w = (P.w + Q.w) * c;
        T1.x = (P.x - Q.x) * c; T1.y = (P.y - Q.y) * c;
        T1.z = (P.z - Q.z) * c; T1.w = (P.w - Q.w) * c;
        tsh4[     sL2 * 8 + oq] = T0;
        tsh4[32 + sL2 * 8 + oq] = T1;
    }
    __syncthreads();

    // ---- add T term + store -------------------------------------------------
    const int pa = aa >> 3;
    float* orow = out + (4 * sg + sL) * XS + n2 * 32;
#pragma unroll
    for (int oo = 0; oo < 4; oo++)
        orow[og + 8 * oo] = acc2[oo] + tshF[pa * 128 + sL * 32 + og + 8 * oo];
}

// ---------------------------------------------------------------------------
extern "C" void kernel_launch(void* const* d_in, const int* in_sizes, int n_in,
                              void* d_out, int out_size)
{
    const float* x      = (const float*)d_in[0];
    const float* w_diag = (const float*)d_in[1];
    const float* w_off  = (const float*)d_in[2];
    const float* b1     = (const float*)d_in[3];
    const int*   perm   = (const int*)d_in[4];
    float* out = (float*)d_out;

    fused_kernel<<<128, 512>>>(x, w_diag, w_off, b1, perm, out);
}